// round 3
// baseline (speedup 1.0000x reference)
#include <cuda_runtime.h>
#include <math.h>

#define C_PROTO 100000
#define D_DIM   256
#define P_PAIRS 65536
#define K_NEG   4
#define BETA    0.1f
#define MARGIN  0.1f
#define EPS     1e-6f

#define NBLOCKS 2048
#define NTHREADS 256
#define NWARPS_TOTAL ((NBLOCKS * NTHREADS) / 32)

// scratch for per-block partial sums (pos_sum, neg_sum) — no allocation allowed
__device__ float2 g_partials[NBLOCKS];

__device__ __forceinline__ float warp_sum(float v) {
#pragma unroll
    for (int o = 16; o > 0; o >>= 1)
        v += __shfl_xor_sync(0xffffffffu, v, o);
    return v;
}

__device__ __forceinline__ float dot4(float4 a, float4 b) {
    return a.x * b.x + a.y * b.y + a.z * b.z + a.w * b.w;
}

__global__ void __launch_bounds__(NTHREADS)
energy_kernel(const float* __restrict__ proto,
              const int*   __restrict__ pairs,
              const int*   __restrict__ negc)
{
    const int lane    = threadIdx.x & 31;
    const int warp_id = (blockIdx.x * NTHREADS + threadIdx.x) >> 5;

    float pos_sum = 0.0f;
    float neg_sum = 0.0f;

    for (int i = warp_id; i < P_PAIRS; i += NWARPS_TOTAL) {
        const int pidx = pairs[2 * i];
        const int cpos = pairs[2 * i + 1];

        // load parent p once; each lane holds 8 floats (two float4 segments)
        const float4* pb = (const float4*)(proto + (size_t)pidx * D_DIM);
        const float4 pa0 = pb[lane];
        const float4 pa1 = pb[lane + 32];

        float pp = dot4(pa0, pa0) + dot4(pa1, pa1);
        pp = warp_sum(pp);                       // uniform across warp
        const float norm_p = sqrtf(pp);
        const float ap_arg = fminf(BETA / (norm_p + EPS), 1.0f - EPS); // arg > 0 always
        const float aperture = asinf(ap_arg);
        const float inv_denom_base = 2.0f * norm_p;

        // 5 children: index 0 = positive, 1..4 = negatives
#pragma unroll
        for (int k = 0; k < 5; k++) {
            const int cidx = (k == 0) ? cpos : negc[4 * i + (k - 1)];
            const float4* cb = (const float4*)(proto + (size_t)cidx * D_DIM);
            const float4 ca0 = cb[lane];
            const float4 ca1 = cb[lane + 32];

            float cc = dot4(ca0, ca0) + dot4(ca1, ca1);
            float4 d0 = make_float4(ca0.x - pa0.x, ca0.y - pa0.y,
                                    ca0.z - pa0.z, ca0.w - pa0.w);
            float4 d1 = make_float4(ca1.x - pa1.x, ca1.y - pa1.y,
                                    ca1.z - pa1.z, ca1.w - pa1.w);
            float dd = dot4(d0, d0) + dot4(d1, d1);

            cc = warp_sum(cc);
            dd = warp_sum(dd);

            const float num   = cc - pp - dd;
            const float denom = inv_denom_base * sqrtf(dd) + EPS;
            float cosang = num / denom;
            cosang = fminf(fmaxf(cosang, -1.0f + EPS), 1.0f - EPS);
            const float ang = acosf(cosang);
            const float e   = fmaxf(ang - aperture, 0.0f);

            if (k == 0) pos_sum += e;
            else        neg_sum += fmaxf(MARGIN - e, 0.0f);
        }
    }

    // block reduction (values are warp-uniform after butterfly reduce)
    __shared__ float2 s[NTHREADS / 32];
    if (lane == 0)
        s[threadIdx.x >> 5] = make_float2(pos_sum, neg_sum);
    __syncthreads();
    if (threadIdx.x == 0) {
        float2 acc = s[0];
#pragma unroll
        for (int w = 1; w < NTHREADS / 32; w++) {
            acc.x += s[w].x;
            acc.y += s[w].y;
        }
        g_partials[blockIdx.x] = acc;
    }
}

__global__ void __launch_bounds__(256)
final_reduce_kernel(float* __restrict__ out)
{
    __shared__ float sx[256];
    __shared__ float sy[256];
    float ax = 0.0f, ay = 0.0f;
    for (int i = threadIdx.x; i < NBLOCKS; i += 256) {
        float2 v = g_partials[i];
        ax += v.x;
        ay += v.y;
    }
    sx[threadIdx.x] = ax;
    sy[threadIdx.x] = ay;
    __syncthreads();
#pragma unroll
    for (int st = 128; st > 0; st >>= 1) {
        if (threadIdx.x < st) {
            sx[threadIdx.x] += sx[threadIdx.x + st];
            sy[threadIdx.x] += sy[threadIdx.x + st];
        }
        __syncthreads();
    }
    if (threadIdx.x == 0) {
        const float avg_pos = sx[0] / (float)P_PAIRS;
        const float avg_neg = sy[0] / (float)(P_PAIRS * K_NEG);
        out[0] = (avg_pos + avg_neg) * 0.5f;
    }
}

extern "C" void kernel_launch(void* const* d_in, const int* in_sizes, int n_in,
                              void* d_out, int out_size)
{
    (void)in_sizes; (void)n_in; (void)out_size;
    const float* proto = (const float*)d_in[0];
    const int*   pairs = (const int*)d_in[1];
    const int*   negc  = (const int*)d_in[2];
    float* out = (float*)d_out;

    energy_kernel<<<NBLOCKS, NTHREADS>>>(proto, pairs, negc);
    final_reduce_kernel<<<1, 256>>>(out);
}

// round 4
// speedup vs baseline: 1.0326x; 1.0326x over previous
#include <cuda_runtime.h>
#include <math.h>

#define C_PROTO 100000
#define D_DIM   256
#define P_PAIRS 65536
#define K_NEG   4
#define BETA    0.1f
#define MARGIN  0.1f
#define EPS     1e-6f

#define NBLOCKS 2048
#define NTHREADS 256
#define NWARPS_TOTAL ((NBLOCKS * NTHREADS) / 32)

// scratch for per-block partial sums (pos_sum, neg_sum) — no allocation allowed
__device__ float2 g_partials[NBLOCKS];
__device__ unsigned int g_count;   // zero at module load; last block resets to 0

__device__ __forceinline__ float warp_sum(float v) {
#pragma unroll
    for (int o = 16; o > 0; o >>= 1)
        v += __shfl_xor_sync(0xffffffffu, v, o);
    return v;
}

__device__ __forceinline__ float dot4(float4 a, float4 b) {
    return a.x * b.x + a.y * b.y + a.z * b.z + a.w * b.w;
}

__global__ void __launch_bounds__(NTHREADS)
energy_kernel(const float* __restrict__ proto,
              const int*   __restrict__ pairs,
              const int*   __restrict__ negc,
              float*       __restrict__ out)
{
    const int lane    = threadIdx.x & 31;
    const int warp_id = (blockIdx.x * NTHREADS + threadIdx.x) >> 5;

    float pos_sum = 0.0f;
    float neg_sum = 0.0f;

    for (int i = warp_id; i < P_PAIRS; i += NWARPS_TOTAL) {
        // indices: one int2 + one int4 load (both naturally aligned)
        const int2 pr = *(const int2*)(pairs + 2 * i);
        const int4 ng = *(const int4*)(negc + 4 * i);
        int cidx[5];
        cidx[0] = pr.y;
        cidx[1] = ng.x; cidx[2] = ng.y; cidx[3] = ng.z; cidx[4] = ng.w;

        // parent vector: 8 floats per lane
        const float4* pb = (const float4*)(proto + (size_t)pr.x * D_DIM);
        const float4 pa0 = pb[lane];
        const float4 pa1 = pb[lane + 32];

        // ---- batch 1: first half of all 5 children (5 back-to-back LDG.128) ----
        float4 ca0[5];
#pragma unroll
        for (int k = 0; k < 5; k++)
            ca0[k] = ((const float4*)(proto + (size_t)cidx[k] * D_DIM))[lane];

        float cc[5], dd[5];
#pragma unroll
        for (int k = 0; k < 5; k++) {
            cc[k] = dot4(ca0[k], ca0[k]);
            float4 d = make_float4(ca0[k].x - pa0.x, ca0[k].y - pa0.y,
                                   ca0[k].z - pa0.z, ca0[k].w - pa0.w);
            dd[k] = dot4(d, d);
        }

        // ---- batch 2: second half of all 5 children ----
        float4 ca1[5];
#pragma unroll
        for (int k = 0; k < 5; k++)
            ca1[k] = ((const float4*)(proto + (size_t)cidx[k] * D_DIM))[lane + 32];

#pragma unroll
        for (int k = 0; k < 5; k++) {
            cc[k] += dot4(ca1[k], ca1[k]);
            float4 d = make_float4(ca1[k].x - pa1.x, ca1[k].y - pa1.y,
                                   ca1[k].z - pa1.z, ca1[k].w - pa1.w);
            dd[k] += dot4(d, d);
        }

        float pp = dot4(pa0, pa0) + dot4(pa1, pa1);

        // ---- 11 independent butterfly reductions (chains overlap) ----
        pp = warp_sum(pp);
#pragma unroll
        for (int k = 0; k < 5; k++) cc[k] = warp_sum(cc[k]);
#pragma unroll
        for (int k = 0; k < 5; k++) dd[k] = warp_sum(dd[k]);

        // ---- scalar epilogue (warp-uniform) ----
        const float norm_p = sqrtf(pp);
        const float ap_arg = fminf(BETA / (norm_p + EPS), 1.0f - EPS);
        const float aperture = asinf(ap_arg);
        const float denom_base = 2.0f * norm_p;

#pragma unroll
        for (int k = 0; k < 5; k++) {
            const float num   = cc[k] - pp - dd[k];
            const float denom = denom_base * sqrtf(dd[k]) + EPS;
            float cosang = num / denom;
            cosang = fminf(fmaxf(cosang, -1.0f + EPS), 1.0f - EPS);
            const float ang = acosf(cosang);
            const float e   = fmaxf(ang - aperture, 0.0f);
            if (k == 0) pos_sum += e;
            else        neg_sum += fmaxf(MARGIN - e, 0.0f);
        }
    }

    // ---- per-block reduction (values warp-uniform after butterfly) ----
    __shared__ float2 s[NTHREADS / 32];
    __shared__ bool   s_last;
    if (lane == 0)
        s[threadIdx.x >> 5] = make_float2(pos_sum, neg_sum);
    __syncthreads();
    if (threadIdx.x == 0) {
        float2 acc = s[0];
#pragma unroll
        for (int w = 1; w < NTHREADS / 32; w++) {
            acc.x += s[w].x;
            acc.y += s[w].y;
        }
        g_partials[blockIdx.x] = acc;
        __threadfence();
        unsigned int t = atomicAdd(&g_count, 1u);
        s_last = (t == (unsigned int)(NBLOCKS - 1));
    }
    __syncthreads();

    // ---- last block performs the deterministic final reduction ----
    if (s_last) {
        __shared__ float sx[NTHREADS];
        __shared__ float sy[NTHREADS];
        float ax = 0.0f, ay = 0.0f;
        for (int b = threadIdx.x; b < NBLOCKS; b += NTHREADS) {
            float2 v = g_partials[b];
            ax += v.x;
            ay += v.y;
        }
        sx[threadIdx.x] = ax;
        sy[threadIdx.x] = ay;
        __syncthreads();
#pragma unroll
        for (int st = NTHREADS / 2; st > 0; st >>= 1) {
            if (threadIdx.x < st) {
                sx[threadIdx.x] += sx[threadIdx.x + st];
                sy[threadIdx.x] += sy[threadIdx.x + st];
            }
            __syncthreads();
        }
        if (threadIdx.x == 0) {
            const float avg_pos = sx[0] / (float)P_PAIRS;
            const float avg_neg = sy[0] / (float)(P_PAIRS * K_NEG);
            out[0] = (avg_pos + avg_neg) * 0.5f;
            g_count = 0;   // reset for next (graph-replayed) launch
        }
    }
}

extern "C" void kernel_launch(void* const* d_in, const int* in_sizes, int n_in,
                              void* d_out, int out_size)
{
    (void)in_sizes; (void)n_in; (void)out_size;
    const float* proto = (const float*)d_in[0];
    const int*   pairs = (const int*)d_in[1];
    const int*   negc  = (const int*)d_in[2];
    float* out = (float*)d_out;

    energy_kernel<<<NBLOCKS, NTHREADS>>>(proto, pairs, negc, out);
}